// round 1
// baseline (speedup 1.0000x reference)
#include <cuda_runtime.h>
#include <cstdint>

#define B_ 64
#define N_ 32
#define H_ 24
#define F_ 256

typedef unsigned long long u64;

// Scratch (device globals: no allocations allowed)
__device__ float g_QWq[(size_t)B_ * N_ * F_];            // 2 MB
__device__ float g_logits[(size_t)B_ * N_ * H_];         // 196 KB
__device__ float g_VWv[(size_t)B_ * N_ * H_ * F_];       // 50 MB

// ---------------- f32x2 packed-math helpers ----------------
__device__ __forceinline__ u64 pack2(float x, float y) {
    u64 r; asm("mov.b64 %0, {%1,%2};" : "=l"(r) : "f"(x), "f"(y)); return r;
}
__device__ __forceinline__ void unpack2(u64 v, float& x, float& y) {
    asm("mov.b64 {%0,%1}, %2;" : "=f"(x), "=f"(y) : "l"(v));
}
__device__ __forceinline__ void fma2(u64& d, u64 a, u64 b) {
    asm("fma.rn.f32x2 %0, %1, %2, %0;" : "+l"(d) : "l"(a), "l"(b));
}

// ---------------- cp.async helpers ----------------
__device__ __forceinline__ uint32_t s2u(const void* p) {
    return (uint32_t)__cvta_generic_to_shared(p);
}
__device__ __forceinline__ void cpasync16(uint32_t dst, const void* src) {
    asm volatile("cp.async.cg.shared.global [%0], [%1], 16;" :: "r"(dst), "l"(src));
}
__device__ __forceinline__ void cpcommit() { asm volatile("cp.async.commit_group;"); }
__device__ __forceinline__ void cpwaitall() { asm volatile("cp.async.wait_all;" ::: "memory"); }

// ---------------- SMEM staging ----------------
// Ad: A chunk transposed AND duplicated: Ad[f][2*b] = Ad[f][2*b+1] = A[b][f]
//     so a warp-broadcast LDS.128 yields ready-made {a,a} pairs for fma2.
// Ws: W chunk natural layout Ws[f][g]; pairs along g feed fma2's b operand.
struct __align__(16) Smem {
    float Ad[2][16][128];   // 16 KB
    float Ws[2][16][256];   // 32 KB
};                          // 48 KB total (static limit)

// ---------------- Core: C[64x256] = A[64x256] @ W[256x256] ----------------
// 256 threads, 8x8 microtile per thread. Thread t: warp tb=t>>5 owns rows
// tb*8..tb*8+7; lane tg=t&31 owns cols tg*8..tg*8+7. acc[i][j2] packs
// {C[i][2j2], C[i][2j2+1]} as f32x2.
__device__ __forceinline__ void gemm_tile(const float* __restrict__ Abase, long strideA,
                                          const float* __restrict__ Wbase,
                                          Smem* sm, u64 acc[8][4])
{
    const int t  = threadIdx.x;
    const int ar = t >> 2;          // A row 0..63
    const int ac = (t & 3) << 2;    // f offset 0,4,8,12 within chunk
    const int wf = t >> 4;          // W chunk row 0..15
    const int wg = (t & 15) << 4;   // W col 0..240
    const int tb = t >> 5;
    const int tg = t & 31;

    #pragma unroll
    for (int i = 0; i < 8; i++)
        #pragma unroll
        for (int j = 0; j < 4; j++) acc[i][j] = 0ULL;

    const float* aPtr = Abase + (long)ar * strideA + ac;
    const float* wPtr = Wbase + (long)wf * F_ + wg;

    // Prologue: stage chunk 0 into buffer 0
    float4 aReg = *(const float4*)aPtr;
    {
        uint32_t wd = s2u(&sm->Ws[0][wf][wg]);
        cpasync16(wd,      wPtr);
        cpasync16(wd + 16, wPtr + 4);
        cpasync16(wd + 32, wPtr + 8);
        cpasync16(wd + 48, wPtr + 12);
        cpcommit();
        u64* AdU = (u64*)sm->Ad[0];
        AdU[(ac + 0) * 64 + ar] = pack2(aReg.x, aReg.x);
        AdU[(ac + 1) * 64 + ar] = pack2(aReg.y, aReg.y);
        AdU[(ac + 2) * 64 + ar] = pack2(aReg.z, aReg.z);
        AdU[(ac + 3) * 64 + ar] = pack2(aReg.w, aReg.w);
    }
    cpwaitall();
    __syncthreads();

    #pragma unroll 2
    for (int c = 0; c < 16; ++c) {
        const int cur = c & 1;
        const int nxt = cur ^ 1;
        if (c + 1 < 16) {   // issue next chunk's loads (latency hidden by compute)
            aReg = *(const float4*)(aPtr + (c + 1) * 16);
            const float* wp = wPtr + (long)(c + 1) * 16 * F_;
            uint32_t wd = s2u(&sm->Ws[nxt][wf][wg]);
            cpasync16(wd,      wp);
            cpasync16(wd + 16, wp + 4);
            cpasync16(wd + 32, wp + 8);
            cpasync16(wd + 48, wp + 12);
            cpcommit();
        }
        const u64* AdU = (const u64*)sm->Ad[cur];
        const u64* WsU = (const u64*)sm->Ws[cur];
        #pragma unroll
        for (int f = 0; f < 16; ++f) {
            u64 ad[8], bs[4];
            const ulonglong2* ap2 = (const ulonglong2*)(AdU + f * 64 + tb * 8);
            ulonglong2 v0 = ap2[0], v1 = ap2[1], v2 = ap2[2], v3 = ap2[3];
            ad[0] = v0.x; ad[1] = v0.y; ad[2] = v1.x; ad[3] = v1.y;
            ad[4] = v2.x; ad[5] = v2.y; ad[6] = v3.x; ad[7] = v3.y;
            const ulonglong2* bp2 = (const ulonglong2*)(WsU + f * 128 + tg * 4);
            ulonglong2 w0 = bp2[0], w1 = bp2[1];
            bs[0] = w0.x; bs[1] = w0.y; bs[2] = w1.x; bs[3] = w1.y;
            #pragma unroll
            for (int i = 0; i < 8; i++) {
                fma2(acc[i][0], ad[i], bs[0]);
                fma2(acc[i][1], ad[i], bs[1]);
                fma2(acc[i][2], ad[i], bs[2]);
                fma2(acc[i][3], ad[i], bs[3]);
            }
        }
        if (c + 1 < 16) {
            u64* AdU2 = (u64*)sm->Ad[nxt];
            AdU2[(ac + 0) * 64 + ar] = pack2(aReg.x, aReg.x);
            AdU2[(ac + 1) * 64 + ar] = pack2(aReg.y, aReg.y);
            AdU2[(ac + 2) * 64 + ar] = pack2(aReg.z, aReg.z);
            AdU2[(ac + 3) * 64 + ar] = pack2(aReg.w, aReg.w);
            cpwaitall();
        }
        __syncthreads();
    }
}

__device__ __forceinline__ void unpack8(const u64 a[4], float c[8]) {
    unpack2(a[0], c[0], c[1]);
    unpack2(a[1], c[2], c[3]);
    unpack2(a[2], c[4], c[5]);
    unpack2(a[3], c[6], c[7]);
}

// ---------------- K1: QWq[b,n,g] = Q[b,n,:]@Wq[n] + bq[n,:] ----------------
__global__ void __launch_bounds__(256, 2) k_qwq(const float* __restrict__ Q,
                                                const float* __restrict__ Wq,
                                                const float* __restrict__ bq)
{
    __shared__ Smem sm;
    const int n = blockIdx.x;
    u64 acc[8][4];
    gemm_tile(Q + (size_t)n * F_, (long)N_ * F_, Wq + (size_t)n * F_ * F_, &sm, acc);
    const int t = threadIdx.x, tb = t >> 5, tg = t & 31;
    const float* bqp = bq + (size_t)n * F_ + tg * 8;
    float4 b0 = *(const float4*)bqp, b1 = *(const float4*)(bqp + 4);
    #pragma unroll
    for (int i = 0; i < 8; i++) {
        float c[8]; unpack8(acc[i], c);
        float4 o0 = make_float4(c[0] + b0.x, c[1] + b0.y, c[2] + b0.z, c[3] + b0.w);
        float4 o1 = make_float4(c[4] + b1.x, c[5] + b1.y, c[6] + b1.z, c[7] + b1.w);
        float* op = g_QWq + ((size_t)(tb * 8 + i) * N_ + n) * F_ + tg * 8;
        *(float4*)op = o0; *(float4*)(op + 4) = o1;
    }
}

// ---------------- K2: per (h,n) CTA: logits + VWv ----------------
__global__ void __launch_bounds__(256, 2) k_kv(const float* __restrict__ Kt,
                                               const float* __restrict__ Vt,
                                               const float* __restrict__ Wk,
                                               const float* __restrict__ bk,
                                               const float* __restrict__ Wv,
                                               const float* __restrict__ bv)
{
    __shared__ Smem sm;
    const int h = blockIdx.x, n = blockIdx.y;
    const int t = threadIdx.x, tb = t >> 5, tg = t & 31;
    u64 acc[8][4];

    // ---- Phase 1: C = K[:,h,n,:] @ Wk[n,h]; logits = rowdot(C+bk, QWq) ----
    gemm_tile(Kt + ((size_t)h * N_ + n) * F_, (long)H_ * N_ * F_,
              Wk + ((size_t)n * H_ + h) * F_ * F_, &sm, acc);
    {
        const float* bkp = bk + ((size_t)n * H_ + h) * F_ + tg * 8;
        float4 k0 = *(const float4*)bkp, k1 = *(const float4*)(bkp + 4);
        float part[8];
        #pragma unroll
        for (int i = 0; i < 8; i++) {
            float c[8]; unpack8(acc[i], c);
            const float* qp = g_QWq + ((size_t)(tb * 8 + i) * N_ + n) * F_ + tg * 8;
            float4 q0 = *(const float4*)qp, q1 = *(const float4*)(qp + 4);
            part[i] = (c[0] + k0.x) * q0.x + (c[1] + k0.y) * q0.y
                    + (c[2] + k0.z) * q0.z + (c[3] + k0.w) * q0.w
                    + (c[4] + k1.x) * q1.x + (c[5] + k1.y) * q1.y
                    + (c[6] + k1.z) * q1.z + (c[7] + k1.w) * q1.w;
        }
        #pragma unroll
        for (int off = 16; off > 0; off >>= 1)
            #pragma unroll
            for (int i = 0; i < 8; i++)
                part[i] += __shfl_xor_sync(0xffffffffu, part[i], off);
        if (tg == 0) {
            #pragma unroll
            for (int i = 0; i < 8; i++)
                g_logits[((size_t)(tb * 8 + i) * N_ + n) * H_ + h] = part[i];
        }
    }
    __syncthreads();

    // ---- Phase 2: VWv[b,n,h,:] = V[:,h,n,:] @ Wv[n,h] + bv ----
    gemm_tile(Vt + ((size_t)h * N_ + n) * F_, (long)H_ * N_ * F_,
              Wv + ((size_t)n * H_ + h) * F_ * F_, &sm, acc);
    {
        const float* bvp = bv + ((size_t)n * H_ + h) * F_ + tg * 8;
        float4 v0 = *(const float4*)bvp, v1 = *(const float4*)(bvp + 4);
        #pragma unroll
        for (int i = 0; i < 8; i++) {
            float c[8]; unpack8(acc[i], c);
            float4 o0 = make_float4(c[0] + v0.x, c[1] + v0.y, c[2] + v0.z, c[3] + v0.w);
            float4 o1 = make_float4(c[4] + v1.x, c[5] + v1.y, c[6] + v1.z, c[7] + v1.w);
            float* op = g_VWv + (((size_t)(tb * 8 + i) * N_ + n) * H_ + h) * F_ + tg * 8;
            *(float4*)op = o0; *(float4*)(op + 4) = o1;
        }
    }
}

// ---------------- K3: softmax over H; write scores to d_out ----------------
__global__ void k_softmax(float* __restrict__ out)
{
    const int idx = blockIdx.x * 256 + threadIdx.x;   // (b*N+n), 0..2047
    const float* lp = g_logits + (size_t)idx * H_;
    float l[H_];
    float m = -3.4e38f;
    #pragma unroll
    for (int h = 0; h < H_; ++h) { l[h] = lp[h]; m = fmaxf(m, l[h]); }
    float s = 0.f;
    #pragma unroll
    for (int h = 0; h < H_; ++h) { l[h] = expf(l[h] - m); s += l[h]; }
    const float inv = 1.0f / s;
    float* sp = out + (size_t)B_ * N_ * F_ + (size_t)idx * H_;
    #pragma unroll
    for (int h = 0; h < H_; ++h) sp[h] = l[h] * inv;
}

// ---------------- K4: heads[b,n,g] = sum_h scores * VWv ----------------
__global__ void k_heads(float* __restrict__ out)
{
    __shared__ float s[H_];
    const int bn = blockIdx.x;          // b*N+n
    const int g = threadIdx.x;          // 0..255
    if (g < H_) s[g] = out[(size_t)B_ * N_ * F_ + (size_t)bn * H_ + g];
    __syncthreads();
    const float* vp = g_VWv + (size_t)bn * H_ * F_ + g;
    float acc = 0.f;
    #pragma unroll
    for (int h = 0; h < H_; ++h) acc += s[h] * vp[(size_t)h * F_];
    out[(size_t)bn * F_ + g] = acc;
}

// ---------------- Launch ----------------
extern "C" void kernel_launch(void* const* d_in, const int* in_sizes, int n_in,
                              void* d_out, int out_size)
{
    (void)in_sizes; (void)n_in; (void)out_size;
    const float* Q  = (const float*)d_in[0];
    const float* K  = (const float*)d_in[1];
    const float* V  = (const float*)d_in[2];
    const float* Wq = (const float*)d_in[3];
    const float* bq = (const float*)d_in[4];
    const float* Wk = (const float*)d_in[5];
    const float* bk = (const float*)d_in[6];
    const float* Wv = (const float*)d_in[7];
    const float* bv = (const float*)d_in[8];
    float* out = (float*)d_out;

    k_qwq<<<N_, 256>>>(Q, Wq, bq);
    k_kv<<<dim3(H_, N_), 256>>>(K, V, Wk, bk, Wv, bv);
    k_softmax<<<(B_ * N_) / 256, 256>>>(out);
    k_heads<<<B_ * N_, 256>>>(out);
}